// round 14
// baseline (speedup 1.0000x reference)
#include <cuda_runtime.h>
#include <cuda_bf16.h>
#include <cuda_fp16.h>
#include <mma.h>
#include <math.h>
#include <stdint.h>

using namespace nvcuda;

#define NN 100000
#define HID 128
#define RR 8
#define LL 2
#define HH 4
#define DD 32
#define EE 625000
#define KB (NN * RR)            // 800000 sort buckets (dst*8 + rel)
#define NB2 782                 // ceil(KB/1024)

// ---------------- scratch (device globals; no allocation) ----------------
__device__ float  g_h[(size_t)NN * HID];
__device__ float  g_kqv[(size_t)NN * 3 * HID];   // fp32 (q part read by qt)
__device__ __half g_kv16[(size_t)NN * 256];      // fp16 k(128) | v(128) for attn gather
__device__ float  g_aggr[(size_t)NN * HID];
__device__ __half g_Qt16[(size_t)KB * HID];      // q~ per run, fp16, prescaled
__device__ float  g_Vr[(size_t)KB * HID];
__device__ float  g_D[(size_t)NN * HH];
__device__ int    g_deg[KB];
__device__ int    g_cur[KB];
__device__ int    g_off[KB + 1];
__device__ int    g_bsum[1024];
__device__ int    g_esrc[EE];
__device__ int    g_runidx[KB];
__device__ int    g_lnode[KB];
__device__ int    g_lcnt[RR];

// ---------------- gather ----------------
__global__ void gather_kernel(const float* __restrict__ emb, const int* __restrict__ x) {
    size_t i = (size_t)blockIdx.x * blockDim.x + threadIdx.x;
    if (i >= (size_t)NN * HID) return;
    int node = (int)(i >> 7);
    int c = (int)(i & 127);
    g_h[i] = emb[(size_t)x[node] * HID + c];
}

// ---------------- counting sort by (dst, rel) -> CSR ----------------
__global__ void zero_deg_kernel() {
    int i = blockIdx.x * blockDim.x + threadIdx.x;
    if (i < KB) g_deg[i] = 0;
    if (i < RR) g_lcnt[i] = 0;
}
__global__ void hist_kernel(const int* __restrict__ ei, const int* __restrict__ et) {
    int e = blockIdx.x * blockDim.x + threadIdx.x;
    if (e < EE) atomicAdd(&g_deg[ei[EE + e] * RR + et[e]], 1);
}
__global__ __launch_bounds__(1024) void scan1_kernel() {
    __shared__ int s[1024];
    int i = blockIdx.x * 1024 + threadIdx.x;
    int v = (i < KB) ? g_deg[i] : 0;
    s[threadIdx.x] = v;
    __syncthreads();
    for (int off = 1; off < 1024; off <<= 1) {
        int t = (threadIdx.x >= off) ? s[threadIdx.x - off] : 0;
        __syncthreads();
        s[threadIdx.x] += t;
        __syncthreads();
    }
    if (i < KB) g_off[i] = s[threadIdx.x] - v;
    if (threadIdx.x == 1023) g_bsum[blockIdx.x] = s[1023];
}
__global__ __launch_bounds__(1024) void scan2_kernel() {
    __shared__ int s[1024];
    int v = (threadIdx.x < NB2) ? g_bsum[threadIdx.x] : 0;
    s[threadIdx.x] = v;
    __syncthreads();
    for (int off = 1; off < 1024; off <<= 1) {
        int t = (threadIdx.x >= off) ? s[threadIdx.x - off] : 0;
        __syncthreads();
        s[threadIdx.x] += t;
        __syncthreads();
    }
    if (threadIdx.x < NB2) g_bsum[threadIdx.x] = s[threadIdx.x] - v;
}
__global__ void scan3_kernel() {
    int i = blockIdx.x * blockDim.x + threadIdx.x;
    if (i < KB) {
        g_off[i] += g_bsum[i >> 10];
        g_cur[i] = 0;
    }
    if (i == 0) g_off[KB] = EE;
}
__global__ void scatter_kernel(const int* __restrict__ ei, const int* __restrict__ et) {
    int e = blockIdx.x * blockDim.x + threadIdx.x;
    if (e >= EE) return;
    int key = ei[EE + e] * RR + et[e];
    int pos = g_off[key] + atomicAdd(&g_cur[key], 1);
    g_esrc[pos] = ei[e];
}
__global__ void build_lists_kernel() {
    int b = blockIdx.x * blockDim.x + threadIdx.x;
    if (b >= KB) return;
    if (g_deg[b] > 0) {
        int r = b & 7;
        int n = b >> 3;
        int idx = atomicAdd(&g_lcnt[r], 1);
        g_runidx[b] = r * NN + idx;
        g_lnode[r * NN + idx] = n;
    } else {
        g_runidx[b] = -1;
    }
}

// =================== WMMA bf16 3M-split GEMMs ===================
#define LDAB 136
#define LDST 132
#define SM_AHI 0
#define SM_ALO 34816
#define SM_BHI 69632
#define SM_BLO 104448
#define SMEM_WMMA 139264

__device__ __forceinline__ void bf16_split(float f, __nv_bfloat16& hi, __nv_bfloat16& lo) {
    hi = __float2bfloat16(f);
    lo = __float2bfloat16(f - __bfloat162float(hi));
}

__device__ __forceinline__ void wmma_chunk_mma(char* smc, float* stage, int warp) {
    const __nv_bfloat16* Ahi = (const __nv_bfloat16*)(smc + SM_AHI);
    const __nv_bfloat16* Alo = (const __nv_bfloat16*)(smc + SM_ALO);
    const __nv_bfloat16* Bhi = (const __nv_bfloat16*)(smc + SM_BHI);
    const __nv_bfloat16* Blo = (const __nv_bfloat16*)(smc + SM_BLO);
    int wm = warp >> 1;
    int wn = warp & 1;

    wmma::fragment<wmma::accumulator, 16, 16, 16, float> c[2][4];
#pragma unroll
    for (int i = 0; i < 2; i++)
#pragma unroll
        for (int j = 0; j < 4; j++) wmma::fill_fragment(c[i][j], 0.f);

    for (int kt = 0; kt < 8; kt++) {
        wmma::fragment<wmma::matrix_a, 16, 16, 16, __nv_bfloat16, wmma::row_major> ahi[2], alo[2];
#pragma unroll
        for (int i = 0; i < 2; i++) {
            int m0 = wm * 32 + i * 16;
            wmma::load_matrix_sync(ahi[i], Ahi + m0 * LDAB + kt * 16, LDAB);
            wmma::load_matrix_sync(alo[i], Alo + m0 * LDAB + kt * 16, LDAB);
        }
#pragma unroll
        for (int j = 0; j < 4; j++) {
            int n0 = wn * 64 + j * 16;
            wmma::fragment<wmma::matrix_b, 16, 16, 16, __nv_bfloat16, wmma::row_major> bhi, blo;
            wmma::load_matrix_sync(bhi, Bhi + kt * 16 * LDAB + n0, LDAB);
            wmma::load_matrix_sync(blo, Blo + kt * 16 * LDAB + n0, LDAB);
#pragma unroll
            for (int i = 0; i < 2; i++) {
                wmma::mma_sync(c[i][j], ahi[i], bhi, c[i][j]);
                wmma::mma_sync(c[i][j], ahi[i], blo, c[i][j]);
                wmma::mma_sync(c[i][j], alo[i], bhi, c[i][j]);
            }
        }
    }
    __syncthreads();
#pragma unroll
    for (int i = 0; i < 2; i++)
#pragma unroll
        for (int j = 0; j < 4; j++) {
            int m0 = wm * 32 + i * 16;
            int n0 = wn * 64 + j * 16;
            wmma::store_matrix_sync(stage + m0 * LDST + n0, c[i][j], LDST, wmma::mem_row_major);
        }
    __syncthreads();
}

// kqv = h @ W_kqv + b ; also emits fp16 k|v copy for attention
__global__ __launch_bounds__(256) void kqv_wmma_kernel(const float* __restrict__ W,
                                                       const float* __restrict__ bias) {
    extern __shared__ char smc[];
    __nv_bfloat16* Ahi = (__nv_bfloat16*)(smc + SM_AHI);
    __nv_bfloat16* Alo = (__nv_bfloat16*)(smc + SM_ALO);
    __nv_bfloat16* Bhi = (__nv_bfloat16*)(smc + SM_BHI);
    __nv_bfloat16* Blo = (__nv_bfloat16*)(smc + SM_BLO);
    float* stage = (float*)(smc + SM_BHI);
    int tid = threadIdx.x;
    int warp = tid >> 5;
    int row0 = blockIdx.x * 128;

    for (int idx = tid; idx < 128 * 128; idx += 256) {
        int row = idx >> 7, col = idx & 127;
        float f = (row0 + row < NN) ? g_h[(size_t)(row0 + row) * 128 + col] : 0.f;
        __nv_bfloat16 hi, lo;
        bf16_split(f, hi, lo);
        Ahi[row * LDAB + col] = hi;
        Alo[row * LDAB + col] = lo;
    }

    for (int chunk = 0; chunk < 3; chunk++) {
        __syncthreads();
        for (int idx = tid; idx < 128 * 128; idx += 256) {
            int k = idx >> 7, n = idx & 127;
            float w = W[k * 384 + chunk * 128 + n];
            __nv_bfloat16 hi, lo;
            bf16_split(w, hi, lo);
            Bhi[k * LDAB + n] = hi;
            Blo[k * LDAB + n] = lo;
        }
        __syncthreads();
        wmma_chunk_mma(smc, stage, warp);
        for (int idx = tid; idx < 128 * 128; idx += 256) {
            int row = idx >> 7, n = idx & 127;
            int grow = row0 + row;
            if (grow < NN) {
                float val = stage[row * LDST + n] + bias[chunk * 128 + n];
                g_kqv[(size_t)grow * 384 + chunk * 128 + n] = val;
                if (chunk == 0)       // k
                    g_kv16[(size_t)grow * 256 + n] = __float2half_rn(val);
                else if (chunk == 2)  // v
                    g_kv16[(size_t)grow * 256 + 128 + n] = __float2half_rn(val);
            }
        }
    }
}

// out: o = gelu(aggr) @ W_out + b; h = relu(sg*o + (1-sg)*h)
__global__ __launch_bounds__(256) void out_wmma_kernel(const float* __restrict__ W,
                                                       const float* __restrict__ bias,
                                                       const float* __restrict__ skip,
                                                       int l, float* __restrict__ out2) {
    extern __shared__ char smc[];
    __nv_bfloat16* Ahi = (__nv_bfloat16*)(smc + SM_AHI);
    __nv_bfloat16* Alo = (__nv_bfloat16*)(smc + SM_ALO);
    __nv_bfloat16* Bhi = (__nv_bfloat16*)(smc + SM_BHI);
    __nv_bfloat16* Blo = (__nv_bfloat16*)(smc + SM_BLO);
    float* stage = (float*)(smc + SM_BHI);
    int tid = threadIdx.x;
    int warp = tid >> 5;
    int row0 = blockIdx.x * 128;

    for (int idx = tid; idx < 128 * 128; idx += 256) {
        int row = idx >> 7, col = idx & 127;
        float f = (row0 + row < NN) ? g_aggr[(size_t)(row0 + row) * 128 + col] : 0.f;
        f = 0.5f * f * (1.f + erff(f * 0.70710678118654752f));   // exact gelu
        __nv_bfloat16 hi, lo;
        bf16_split(f, hi, lo);
        Ahi[row * LDAB + col] = hi;
        Alo[row * LDAB + col] = lo;
    }
    for (int idx = tid; idx < 128 * 128; idx += 256) {
        int k = idx >> 7, n = idx & 127;
        float w = W[k * 128 + n];
        __nv_bfloat16 hi, lo;
        bf16_split(w, hi, lo);
        Bhi[k * LDAB + n] = hi;
        Blo[k * LDAB + n] = lo;
    }
    __syncthreads();
    wmma_chunk_mma(smc, stage, warp);

    float sg = 1.f / (1.f + expf(-skip[l]));
    for (int idx = tid; idx < 128 * 128; idx += 256) {
        int row = idx >> 7, n = idx & 127;
        int grow = row0 + row;
        if (grow < NN) {
            float o = stage[row * LDST + n] + bias[n];
            float* hp = g_h + (size_t)grow * 128 + n;
            float hn = fmaxf(sg * o + (1.f - sg) * (*hp), 0.f);
            *hp = hn;
            if (out2) out2[(size_t)grow * 128 + n] = hn;
        }
    }
}

// ---------------- q~ = (pr*scale) * Wk[r] q[n] per nonempty run -> fp16 ----------------
__global__ __launch_bounds__(256) void qt_kernel(const float* __restrict__ Wk,
                                                 const float* __restrict__ pr) {
    extern __shared__ float sm[];
    float* WkT = sm;            // 4096
    float* As = sm + 4096;      // 64*129
    int tid = threadIdx.x;
    int r = blockIdx.y;
    int cnt = g_lcnt[r];
    int e0 = blockIdx.x * 64;
    if (e0 >= cnt) return;

    const float* WkR = Wk + (size_t)r * 4096;   // [h][d][f]
    for (int i = tid; i < 4096; i += 256) {
        int h = i >> 10, rem = i & 1023, d = rem >> 5, f = rem & 31;
        WkT[h * 1024 + f * 32 + d] = WkR[i];
    }
    for (int i = tid; i < 64 * 32; i += 256) {
        int row = i >> 5, c4 = i & 31;
        int entry = e0 + row;
        float4 v = make_float4(0.f, 0.f, 0.f, 0.f);
        if (entry < cnt) {
            int n = g_lnode[r * NN + entry];
            v = ((const float4*)(g_kqv + (size_t)n * 384 + 128))[c4];
        }
        float* d = As + row * 129 + c4 * 4;
        d[0] = v.x; d[1] = v.y; d[2] = v.z; d[3] = v.w;
    }
    __syncthreads();

    int i = tid & 63, h = tid >> 6;
    int entry = e0 + i;
    float acc[32];
#pragma unroll
    for (int c = 0; c < 32; c++) acc[c] = 0.f;
    const float* qrow = As + i * 129 + h * 32;
    for (int f = 0; f < 32; f++) {
        float a = qrow[f];
        const float4* w4 = (const float4*)(WkT + h * 1024 + f * 32);
#pragma unroll
        for (int j = 0; j < 8; j++) {
            float4 w = w4[j];
            acc[j * 4 + 0] = fmaf(a, w.x, acc[j * 4 + 0]);
            acc[j * 4 + 1] = fmaf(a, w.y, acc[j * 4 + 1]);
            acc[j * 4 + 2] = fmaf(a, w.z, acc[j * 4 + 2]);
            acc[j * 4 + 3] = fmaf(a, w.w, acc[j * 4 + 3]);
        }
    }
    if (entry < cnt) {
        float prscale = pr[r * 4 + h] * 0.17677669529663689f;   // pr * 1/sqrt(32)
        __half* o = g_Qt16 + ((size_t)(r * NN + entry)) * 128 + h * 32;
#pragma unroll
        for (int c = 0; c < 32; c++) o[c] = __float2half_rn(acc[c] * prscale);
    }
}

// ---------------- attention: warp per dst node, fp16 gather, linear exp-sum ------------
__global__ __launch_bounds__(256) void attn_kernel() {
    int n = (blockIdx.x * blockDim.x + threadIdx.x) >> 5;
    int lane = threadIdx.x & 31;
    if (n >= NN) return;
    const unsigned FULL = 0xffffffffu;

    float D0 = 0.f, D1 = 0.f, D2 = 0.f, D3 = 0.f;
    int base = n * RR;
    for (int r = 0; r < RR; r++) {
        int beg = g_off[base + r];
        int end = g_off[base + r + 1];
        if (beg == end) continue;
        int ridx = g_runidx[base + r];
        const __half* qt = g_Qt16 + (size_t)ridx * 128;
        float qt0 = __half2float(qt[lane]);
        float qt1 = __half2float(qt[32 + lane]);
        float qt2 = __half2float(qt[64 + lane]);
        float qt3 = __half2float(qt[96 + lane]);

        float rd0 = 0.f, rd1 = 0.f, rd2 = 0.f, rd3 = 0.f;
        float ra0 = 0.f, ra1 = 0.f, ra2 = 0.f, ra3 = 0.f;

        for (int e = beg; e < end; e++) {
            int src = g_esrc[e];
            const __half* kb = g_kv16 + (size_t)src * 256;
            float k0 = __half2float(kb[lane]);
            float k1 = __half2float(kb[32 + lane]);
            float k2 = __half2float(kb[64 + lane]);
            float k3 = __half2float(kb[96 + lane]);
            float v0 = __half2float(kb[128 + lane]);
            float v1 = __half2float(kb[160 + lane]);
            float v2 = __half2float(kb[192 + lane]);
            float v3 = __half2float(kb[224 + lane]);
            float p0 = k0 * qt0, p1 = k1 * qt1, p2 = k2 * qt2, p3 = k3 * qt3;
#pragma unroll
            for (int off = 16; off > 0; off >>= 1) {
                p0 += __shfl_xor_sync(FULL, p0, off);
                p1 += __shfl_xor_sync(FULL, p1, off);
                p2 += __shfl_xor_sync(FULL, p2, off);
                p3 += __shfl_xor_sync(FULL, p3, off);
            }
            float w0 = __expf(p0), w1 = __expf(p1), w2 = __expf(p2), w3 = __expf(p3);
            rd0 += w0; ra0 = fmaf(w0, v0, ra0);
            rd1 += w1; ra1 = fmaf(w1, v1, ra1);
            rd2 += w2; ra2 = fmaf(w2, v2, ra2);
            rd3 += w3; ra3 = fmaf(w3, v3, ra3);
        }
        D0 += rd0; D1 += rd1; D2 += rd2; D3 += rd3;
        float* vr = g_Vr + (size_t)ridx * 128;
        vr[lane] = ra0; vr[32 + lane] = ra1; vr[64 + lane] = ra2; vr[96 + lane] = ra3;
    }
    if (lane == 0) {
        g_D[(size_t)n * 4 + 0] = D0;
        g_D[(size_t)n * 4 + 1] = D1;
        g_D[(size_t)n * 4 + 2] = D2;
        g_D[(size_t)n * 4 + 3] = D3;
    }
}

// ---------------- apply Wv[r] to raw per-run v-sums in place ----------------
__global__ __launch_bounds__(256) void vt_kernel(const float* __restrict__ Wv) {
    extern __shared__ float sm[];
    float* WvS = sm;            // 4096 : [h][d][f]
    float* As = sm + 4096;      // 64*129
    int tid = threadIdx.x;
    int r = blockIdx.y;
    int cnt = g_lcnt[r];
    int e0 = blockIdx.x * 64;
    if (e0 >= cnt) return;

    const float* WvR = Wv + (size_t)r * 4096;
    for (int i = tid; i < 4096; i += 256) WvS[i] = WvR[i];
    for (int i = tid; i < 64 * 32; i += 256) {
        int row = i >> 5, c4 = i & 31;
        int entry = e0 + row;
        float4 v = make_float4(0.f, 0.f, 0.f, 0.f);
        if (entry < cnt)
            v = ((const float4*)(g_Vr + ((size_t)(r * NN + entry)) * 128))[c4];
        float* d = As + row * 129 + c4 * 4;
        d[0] = v.x; d[1] = v.y; d[2] = v.z; d[3] = v.w;
    }
    __syncthreads();

    int i = tid & 63, h = tid >> 6;
    int entry = e0 + i;
    float acc[32];
#pragma unroll
    for (int c = 0; c < 32; c++) acc[c] = 0.f;
    const float* arow = As + i * 129 + h * 32;
    for (int d = 0; d < 32; d++) {
        float a = arow[d];
        const float4* w4 = (const float4*)(WvS + h * 1024 + d * 32);
#pragma unroll
        for (int j = 0; j < 8; j++) {
            float4 w = w4[j];
            acc[j * 4 + 0] = fmaf(a, w.x, acc[j * 4 + 0]);
            acc[j * 4 + 1] = fmaf(a, w.y, acc[j * 4 + 1]);
            acc[j * 4 + 2] = fmaf(a, w.z, acc[j * 4 + 2]);
            acc[j * 4 + 3] = fmaf(a, w.w, acc[j * 4 + 3]);
        }
    }
    if (entry < cnt) {
        float* o = g_Vr + ((size_t)(r * NN + entry)) * 128 + h * 32;
#pragma unroll
        for (int c = 0; c < 32; c++) o[c] = acc[c];
    }
}

// ---------------- merge: plain sum over runs, divide by D ----------------
__global__ __launch_bounds__(256) void merge_kernel() {
    int n = (blockIdx.x * blockDim.x + threadIdx.x) >> 5;
    int lane = threadIdx.x & 31;
    if (n >= NN) return;

    float O0 = 0.f, O1 = 0.f, O2 = 0.f, O3 = 0.f;
    int base = n * RR;
    for (int r = 0; r < RR; r++) {
        int ridx = g_runidx[base + r];
        if (ridx < 0) continue;
        const float* vr = g_Vr + (size_t)ridx * 128;
        O0 += vr[lane]; O1 += vr[32 + lane]; O2 += vr[64 + lane]; O3 += vr[96 + lane];
    }
    float d0 = g_D[(size_t)n * 4 + 0], d1 = g_D[(size_t)n * 4 + 1];
    float d2 = g_D[(size_t)n * 4 + 2], d3 = g_D[(size_t)n * 4 + 3];
    float* og = g_aggr + (size_t)n * 128;
    og[lane]      = (d0 > 0.f) ? O0 / d0 : 0.f;
    og[32 + lane] = (d1 > 0.f) ? O1 / d1 : 0.f;
    og[64 + lane] = (d2 > 0.f) ? O2 / d2 : 0.f;
    og[96 + lane] = (d3 > 0.f) ? O3 / d3 : 0.f;
}

// ---------------- host ----------------
extern "C" void kernel_launch(void* const* d_in, const int* in_sizes, int n_in,
                              void* d_out, int out_size) {
    const float* emb   = (const float*)d_in[0];
    const float* W_kqv = (const float*)d_in[1];
    const float* b_kqv = (const float*)d_in[2];
    const float* Wk    = (const float*)d_in[3];
    const float* Wv    = (const float*)d_in[4];
    const float* p_rel = (const float*)d_in[5];
    const float* W_out = (const float*)d_in[6];
    const float* b_out = (const float*)d_in[7];
    const float* skip  = (const float*)d_in[8];
    const int*   x     = (const int*)d_in[9];
    const int*   ei    = (const int*)d_in[10];
    const int*   et    = (const int*)d_in[11];
    float* out = (float*)d_out;

    const int SMEM_QT = (4096 + 64 * 129) * 4;           // 49408
    static bool attr_set = false;
    if (!attr_set) {
        cudaFuncSetAttribute(kqv_wmma_kernel, cudaFuncAttributeMaxDynamicSharedMemorySize, SMEM_WMMA);
        cudaFuncSetAttribute(out_wmma_kernel, cudaFuncAttributeMaxDynamicSharedMemorySize, SMEM_WMMA);
        cudaFuncSetAttribute(qt_kernel, cudaFuncAttributeMaxDynamicSharedMemorySize, SMEM_QT);
        cudaFuncSetAttribute(vt_kernel, cudaFuncAttributeMaxDynamicSharedMemorySize, SMEM_QT);
        attr_set = true;
    }

    const int nblocks_nh  = (NN * HID + 255) / 256;
    const int nblocks_tc  = (NN + 127) / 128;            // 782
    const int nblocks_qt  = (NN + 63) / 64;              // 1563
    const int nblocks_e   = (EE + 255) / 256;
    const int nblocks_kb  = (KB + 255) / 256;
    const int nblocks_kb1 = (KB + 1 + 255) / 256;
    const int nblocks_w   = (NN * 32 + 255) / 256;       // warp per node

    gather_kernel<<<nblocks_nh, 256>>>(emb, x);

    // sort edges by (dst, rel) into CSR + compact run lists
    zero_deg_kernel<<<nblocks_kb, 256>>>();
    hist_kernel<<<nblocks_e, 256>>>(ei, et);
    scan1_kernel<<<NB2, 1024>>>();
    scan2_kernel<<<1, 1024>>>();
    scan3_kernel<<<nblocks_kb1, 256>>>();
    scatter_kernel<<<nblocks_e, 256>>>(ei, et);
    build_lists_kernel<<<nblocks_kb, 256>>>();

    dim3 tg(nblocks_qt, RR);
    for (int l = 0; l < LL; l++) {
        const float* Wkqv_l = W_kqv + (size_t)l * HID * 3 * HID;
        const float* bkqv_l = b_kqv + (size_t)l * 3 * HID;
        const float* Wk_l   = Wk + (size_t)l * RR * HH * DD * DD;
        const float* Wv_l   = Wv + (size_t)l * RR * HH * DD * DD;
        const float* pr_l   = p_rel + (size_t)l * RR * HH;
        const float* Wout_l = W_out + (size_t)l * HID * HID;
        const float* bout_l = b_out + (size_t)l * HID;

        kqv_wmma_kernel<<<nblocks_tc, 256, SMEM_WMMA>>>(Wkqv_l, bkqv_l);
        qt_kernel<<<tg, 256, SMEM_QT>>>(Wk_l, pr_l);
        attn_kernel<<<nblocks_w, 256>>>();
        vt_kernel<<<tg, 256, SMEM_QT>>>(Wv_l);
        merge_kernel<<<nblocks_w, 256>>>();
        out_wmma_kernel<<<nblocks_tc, 256, SMEM_WMMA>>>(Wout_l, bout_l, skip, l,
                                                        (l == LL - 1) ? out : nullptr);
    }
}

// round 15
// speedup vs baseline: 1.1433x; 1.1433x over previous
#include <cuda_runtime.h>
#include <cuda_bf16.h>
#include <mma.h>
#include <math.h>
#include <stdint.h>

using namespace nvcuda;

#define NN 100000
#define HID 128
#define RR 8
#define LL 2
#define HH 4
#define DD 32
#define EE 625000
#define KB (NN * RR)            // 800000 sort buckets (dst*8 + rel)
#define NB2 782                 // ceil(KB/1024)

// ---------------- scratch (device globals; no allocation) ----------------
__device__ float g_h[(size_t)NN * HID];
__device__ float g_kqv[(size_t)NN * 3 * HID];
__device__ float g_aggr[(size_t)NN * HID];
__device__ float g_Qt[(size_t)KB * HID];    // q~ per run, prescaled by pr/sqrt(D)
__device__ float g_Vr[(size_t)KB * HID];
__device__ float g_D[(size_t)NN * HH];
__device__ int   g_deg[KB];
__device__ int   g_cur[KB];
__device__ int   g_off[KB + 1];
__device__ int   g_bsum[1024];
__device__ int   g_esrc[EE];
__device__ int   g_runidx[KB];
__device__ int   g_lnode[KB];
__device__ int   g_lcnt[RR];

// ---------------- gather ----------------
__global__ void gather_kernel(const float* __restrict__ emb, const int* __restrict__ x) {
    size_t i = (size_t)blockIdx.x * blockDim.x + threadIdx.x;
    if (i >= (size_t)NN * HID) return;
    int node = (int)(i >> 7);
    int c = (int)(i & 127);
    g_h[i] = emb[(size_t)x[node] * HID + c];
}

// ---------------- counting sort by (dst, rel) -> CSR ----------------
__global__ void zero_deg_kernel() {
    int i = blockIdx.x * blockDim.x + threadIdx.x;
    if (i < KB) g_deg[i] = 0;
    if (i < RR) g_lcnt[i] = 0;
}
__global__ void hist_kernel(const int* __restrict__ ei, const int* __restrict__ et) {
    int e = blockIdx.x * blockDim.x + threadIdx.x;
    if (e < EE) atomicAdd(&g_deg[ei[EE + e] * RR + et[e]], 1);
}
__global__ __launch_bounds__(1024) void scan1_kernel() {
    __shared__ int s[1024];
    int i = blockIdx.x * 1024 + threadIdx.x;
    int v = (i < KB) ? g_deg[i] : 0;
    s[threadIdx.x] = v;
    __syncthreads();
    for (int off = 1; off < 1024; off <<= 1) {
        int t = (threadIdx.x >= off) ? s[threadIdx.x - off] : 0;
        __syncthreads();
        s[threadIdx.x] += t;
        __syncthreads();
    }
    if (i < KB) g_off[i] = s[threadIdx.x] - v;
    if (threadIdx.x == 1023) g_bsum[blockIdx.x] = s[1023];
}
__global__ __launch_bounds__(1024) void scan2_kernel() {
    __shared__ int s[1024];
    int v = (threadIdx.x < NB2) ? g_bsum[threadIdx.x] : 0;
    s[threadIdx.x] = v;
    __syncthreads();
    for (int off = 1; off < 1024; off <<= 1) {
        int t = (threadIdx.x >= off) ? s[threadIdx.x - off] : 0;
        __syncthreads();
        s[threadIdx.x] += t;
        __syncthreads();
    }
    if (threadIdx.x < NB2) g_bsum[threadIdx.x] = s[threadIdx.x] - v;
}
__global__ void scan3_kernel() {
    int i = blockIdx.x * blockDim.x + threadIdx.x;
    if (i < KB) {
        g_off[i] += g_bsum[i >> 10];
        g_cur[i] = 0;
    }
    if (i == 0) g_off[KB] = EE;
}
__global__ void scatter_kernel(const int* __restrict__ ei, const int* __restrict__ et) {
    int e = blockIdx.x * blockDim.x + threadIdx.x;
    if (e >= EE) return;
    int key = ei[EE + e] * RR + et[e];
    int pos = g_off[key] + atomicAdd(&g_cur[key], 1);
    g_esrc[pos] = ei[e];
}
__global__ void build_lists_kernel() {
    int b = blockIdx.x * blockDim.x + threadIdx.x;
    if (b >= KB) return;
    if (g_deg[b] > 0) {
        int r = b & 7;
        int n = b >> 3;
        int idx = atomicAdd(&g_lcnt[r], 1);
        g_runidx[b] = r * NN + idx;
        g_lnode[r * NN + idx] = n;
    } else {
        g_runidx[b] = -1;
    }
}

// =================== WMMA bf16 3M-split GEMMs (R12, measured best) ===================
#define LDAB 136
#define LDST 132
#define SM_AHI 0
#define SM_ALO 34816
#define SM_BHI 69632
#define SM_BLO 104448
#define SMEM_WMMA 139264

__device__ __forceinline__ void bf16_split(float f, __nv_bfloat16& hi, __nv_bfloat16& lo) {
    hi = __float2bfloat16(f);
    lo = __float2bfloat16(f - __bfloat162float(hi));
}

__device__ __forceinline__ void wmma_chunk_mma(char* smc, float* stage, int warp) {
    const __nv_bfloat16* Ahi = (const __nv_bfloat16*)(smc + SM_AHI);
    const __nv_bfloat16* Alo = (const __nv_bfloat16*)(smc + SM_ALO);
    const __nv_bfloat16* Bhi = (const __nv_bfloat16*)(smc + SM_BHI);
    const __nv_bfloat16* Blo = (const __nv_bfloat16*)(smc + SM_BLO);
    int wm = warp >> 1;
    int wn = warp & 1;

    wmma::fragment<wmma::accumulator, 16, 16, 16, float> c[2][4];
#pragma unroll
    for (int i = 0; i < 2; i++)
#pragma unroll
        for (int j = 0; j < 4; j++) wmma::fill_fragment(c[i][j], 0.f);

    for (int kt = 0; kt < 8; kt++) {
        wmma::fragment<wmma::matrix_a, 16, 16, 16, __nv_bfloat16, wmma::row_major> ahi[2], alo[2];
#pragma unroll
        for (int i = 0; i < 2; i++) {
            int m0 = wm * 32 + i * 16;
            wmma::load_matrix_sync(ahi[i], Ahi + m0 * LDAB + kt * 16, LDAB);
            wmma::load_matrix_sync(alo[i], Alo + m0 * LDAB + kt * 16, LDAB);
        }
#pragma unroll
        for (int j = 0; j < 4; j++) {
            int n0 = wn * 64 + j * 16;
            wmma::fragment<wmma::matrix_b, 16, 16, 16, __nv_bfloat16, wmma::row_major> bhi, blo;
            wmma::load_matrix_sync(bhi, Bhi + kt * 16 * LDAB + n0, LDAB);
            wmma::load_matrix_sync(blo, Blo + kt * 16 * LDAB + n0, LDAB);
#pragma unroll
            for (int i = 0; i < 2; i++) {
                wmma::mma_sync(c[i][j], ahi[i], bhi, c[i][j]);
                wmma::mma_sync(c[i][j], ahi[i], blo, c[i][j]);
                wmma::mma_sync(c[i][j], alo[i], bhi, c[i][j]);
            }
        }
    }
    __syncthreads();
#pragma unroll
    for (int i = 0; i < 2; i++)
#pragma unroll
        for (int j = 0; j < 4; j++) {
            int m0 = wm * 32 + i * 16;
            int n0 = wn * 64 + j * 16;
            wmma::store_matrix_sync(stage + m0 * LDST + n0, c[i][j], LDST, wmma::mem_row_major);
        }
    __syncthreads();
}

// kqv = h @ W_kqv + b : N=384 in 3 chunks of 128
__global__ __launch_bounds__(256) void kqv_wmma_kernel(const float* __restrict__ W,
                                                       const float* __restrict__ bias) {
    extern __shared__ char smc[];
    __nv_bfloat16* Ahi = (__nv_bfloat16*)(smc + SM_AHI);
    __nv_bfloat16* Alo = (__nv_bfloat16*)(smc + SM_ALO);
    __nv_bfloat16* Bhi = (__nv_bfloat16*)(smc + SM_BHI);
    __nv_bfloat16* Blo = (__nv_bfloat16*)(smc + SM_BLO);
    float* stage = (float*)(smc + SM_BHI);
    int tid = threadIdx.x;
    int warp = tid >> 5;
    int row0 = blockIdx.x * 128;

    for (int idx = tid; idx < 128 * 128; idx += 256) {
        int row = idx >> 7, col = idx & 127;
        float f = (row0 + row < NN) ? g_h[(size_t)(row0 + row) * 128 + col] : 0.f;
        __nv_bfloat16 hi, lo;
        bf16_split(f, hi, lo);
        Ahi[row * LDAB + col] = hi;
        Alo[row * LDAB + col] = lo;
    }

    for (int chunk = 0; chunk < 3; chunk++) {
        __syncthreads();
        for (int idx = tid; idx < 128 * 128; idx += 256) {
            int k = idx >> 7, n = idx & 127;
            float w = W[k * 384 + chunk * 128 + n];
            __nv_bfloat16 hi, lo;
            bf16_split(w, hi, lo);
            Bhi[k * LDAB + n] = hi;
            Blo[k * LDAB + n] = lo;
        }
        __syncthreads();
        wmma_chunk_mma(smc, stage, warp);
        for (int idx = tid; idx < 128 * 128; idx += 256) {
            int row = idx >> 7, n = idx & 127;
            int grow = row0 + row;
            if (grow < NN)
                g_kqv[(size_t)grow * 384 + chunk * 128 + n] =
                    stage[row * LDST + n] + bias[chunk * 128 + n];
        }
    }
}

// out: o = gelu(aggr) @ W_out + b; h = relu(sg*o + (1-sg)*h)
__global__ __launch_bounds__(256) void out_wmma_kernel(const float* __restrict__ W,
                                                       const float* __restrict__ bias,
                                                       const float* __restrict__ skip,
                                                       int l, float* __restrict__ out2) {
    extern __shared__ char smc[];
    __nv_bfloat16* Ahi = (__nv_bfloat16*)(smc + SM_AHI);
    __nv_bfloat16* Alo = (__nv_bfloat16*)(smc + SM_ALO);
    __nv_bfloat16* Bhi = (__nv_bfloat16*)(smc + SM_BHI);
    __nv_bfloat16* Blo = (__nv_bfloat16*)(smc + SM_BLO);
    float* stage = (float*)(smc + SM_BHI);
    int tid = threadIdx.x;
    int warp = tid >> 5;
    int row0 = blockIdx.x * 128;

    for (int idx = tid; idx < 128 * 128; idx += 256) {
        int row = idx >> 7, col = idx & 127;
        float f = (row0 + row < NN) ? g_aggr[(size_t)(row0 + row) * 128 + col] : 0.f;
        f = 0.5f * f * (1.f + erff(f * 0.70710678118654752f));   // exact gelu
        __nv_bfloat16 hi, lo;
        bf16_split(f, hi, lo);
        Ahi[row * LDAB + col] = hi;
        Alo[row * LDAB + col] = lo;
    }
    for (int idx = tid; idx < 128 * 128; idx += 256) {
        int k = idx >> 7, n = idx & 127;
        float w = W[k * 128 + n];
        __nv_bfloat16 hi, lo;
        bf16_split(w, hi, lo);
        Bhi[k * LDAB + n] = hi;
        Blo[k * LDAB + n] = lo;
    }
    __syncthreads();
    wmma_chunk_mma(smc, stage, warp);

    float sg = 1.f / (1.f + expf(-skip[l]));
    for (int idx = tid; idx < 128 * 128; idx += 256) {
        int row = idx >> 7, n = idx & 127;
        int grow = row0 + row;
        if (grow < NN) {
            float o = stage[row * LDST + n] + bias[n];
            float* hp = g_h + (size_t)grow * 128 + n;
            float hn = fmaxf(sg * o + (1.f - sg) * (*hp), 0.f);
            *hp = hn;
            if (out2) out2[(size_t)grow * 128 + n] = hn;
        }
    }
}

// ---------------- q~ = (pr*scale) * Wk[r] q[n] per nonempty run ----------------
__global__ __launch_bounds__(256) void qt_kernel(const float* __restrict__ Wk,
                                                 const float* __restrict__ pr) {
    extern __shared__ float sm[];
    float* WkT = sm;            // 4096
    float* As = sm + 4096;      // 64*129
    int tid = threadIdx.x;
    int r = blockIdx.y;
    int cnt = g_lcnt[r];
    int e0 = blockIdx.x * 64;
    if (e0 >= cnt) return;

    const float* WkR = Wk + (size_t)r * 4096;   // [h][d][f]
    for (int i = tid; i < 4096; i += 256) {
        int h = i >> 10, rem = i & 1023, d = rem >> 5, f = rem & 31;
        WkT[h * 1024 + f * 32 + d] = WkR[i];
    }
    for (int i = tid; i < 64 * 32; i += 256) {
        int row = i >> 5, c4 = i & 31;
        int entry = e0 + row;
        float4 v = make_float4(0.f, 0.f, 0.f, 0.f);
        if (entry < cnt) {
            int n = g_lnode[r * NN + entry];
            v = ((const float4*)(g_kqv + (size_t)n * 384 + 128))[c4];
        }
        float* d = As + row * 129 + c4 * 4;
        d[0] = v.x; d[1] = v.y; d[2] = v.z; d[3] = v.w;
    }
    __syncthreads();

    int i = tid & 63, h = tid >> 6;
    int entry = e0 + i;
    float acc[32];
#pragma unroll
    for (int c = 0; c < 32; c++) acc[c] = 0.f;
    const float* qrow = As + i * 129 + h * 32;
    for (int f = 0; f < 32; f++) {
        float a = qrow[f];
        const float4* w4 = (const float4*)(WkT + h * 1024 + f * 32);
#pragma unroll
        for (int j = 0; j < 8; j++) {
            float4 w = w4[j];
            acc[j * 4 + 0] = fmaf(a, w.x, acc[j * 4 + 0]);
            acc[j * 4 + 1] = fmaf(a, w.y, acc[j * 4 + 1]);
            acc[j * 4 + 2] = fmaf(a, w.z, acc[j * 4 + 2]);
            acc[j * 4 + 3] = fmaf(a, w.w, acc[j * 4 + 3]);
        }
    }
    if (entry < cnt) {
        float prscale = pr[r * 4 + h] * 0.17677669529663689f;   // pr * 1/sqrt(32)
        float* o = g_Qt + ((size_t)(r * NN + entry)) * 128 + h * 32;
#pragma unroll
        for (int c = 0; c < 32; c++) o[c] = acc[c] * prscale;
    }
}

// ---------------- attention: warp/node, lane owns 4 dims, 8-lane segmented reduce ------
// lane l -> dims [4l,4l+3] of [H*D]=128; head = l>>3. All 8 lanes of a group share w.
__global__ __launch_bounds__(256) void attn_kernel() {
    int n = (blockIdx.x * blockDim.x + threadIdx.x) >> 5;
    int lane = threadIdx.x & 31;
    if (n >= NN) return;
    const unsigned FULL = 0xffffffffu;

    float D = 0.f;                      // per-lane copy of its head's denominator
    int base = n * RR;
    for (int r = 0; r < RR; r++) {
        int beg = g_off[base + r];
        int end = g_off[base + r + 1];
        if (beg == end) continue;
        int ridx = g_runidx[base + r];
        float4 qt = ((const float4*)(g_Qt + (size_t)ridx * 128))[lane];

        float rd = 0.f;
        float4 ra = make_float4(0.f, 0.f, 0.f, 0.f);

        for (int e = beg; e < end; e++) {
            int src = g_esrc[e];
            const float4* kb = (const float4*)(g_kqv + (size_t)src * 384);
            float4 k = kb[lane];        // k floats [4l,4l+3]
            float4 v = kb[64 + lane];   // v floats [256+4l ...]
            float p = k.x * qt.x;
            p = fmaf(k.y, qt.y, p);
            p = fmaf(k.z, qt.z, p);
            p = fmaf(k.w, qt.w, p);
            p += __shfl_xor_sync(FULL, p, 1);
            p += __shfl_xor_sync(FULL, p, 2);
            p += __shfl_xor_sync(FULL, p, 4);
            float w = __expf(p);
            rd += w;
            ra.x = fmaf(w, v.x, ra.x);
            ra.y = fmaf(w, v.y, ra.y);
            ra.z = fmaf(w, v.z, ra.z);
            ra.w = fmaf(w, v.w, ra.w);
        }
        D += rd;
        ((float4*)(g_Vr + (size_t)ridx * 128))[lane] = ra;
    }
    if ((lane & 7) == 0) g_D[(size_t)n * 4 + (lane >> 3)] = D;
}

// ---------------- apply Wv[r] to raw per-run v-sums in place ----------------
__global__ __launch_bounds__(256) void vt_kernel(const float* __restrict__ Wv) {
    extern __shared__ float sm[];
    float* WvS = sm;            // 4096 : [h][d][f]
    float* As = sm + 4096;      // 64*129
    int tid = threadIdx.x;
    int r = blockIdx.y;
    int cnt = g_lcnt[r];
    int e0 = blockIdx.x * 64;
    if (e0 >= cnt) return;

    const float* WvR = Wv + (size_t)r * 4096;
    for (int i = tid; i < 4096; i += 256) WvS[i] = WvR[i];
    for (int i = tid; i < 64 * 32; i += 256) {
        int row = i >> 5, c4 = i & 31;
        int entry = e0 + row;
        float4 v = make_float4(0.f, 0.f, 0.f, 0.f);
        if (entry < cnt)
            v = ((const float4*)(g_Vr + ((size_t)(r * NN + entry)) * 128))[c4];
        float* d = As + row * 129 + c4 * 4;
        d[0] = v.x; d[1] = v.y; d[2] = v.z; d[3] = v.w;
    }
    __syncthreads();

    int i = tid & 63, h = tid >> 6;
    int entry = e0 + i;
    float acc[32];
#pragma unroll
    for (int c = 0; c < 32; c++) acc[c] = 0.f;
    const float* arow = As + i * 129 + h * 32;
    for (int d = 0; d < 32; d++) {
        float a = arow[d];
        const float4* w4 = (const float4*)(WvS + h * 1024 + d * 32);
#pragma unroll
        for (int j = 0; j < 8; j++) {
            float4 w = w4[j];
            acc[j * 4 + 0] = fmaf(a, w.x, acc[j * 4 + 0]);
            acc[j * 4 + 1] = fmaf(a, w.y, acc[j * 4 + 1]);
            acc[j * 4 + 2] = fmaf(a, w.z, acc[j * 4 + 2]);
            acc[j * 4 + 3] = fmaf(a, w.w, acc[j * 4 + 3]);
        }
    }
    if (entry < cnt) {
        float* o = g_Vr + ((size_t)(r * NN + entry)) * 128 + h * 32;
#pragma unroll
        for (int c = 0; c < 32; c++) o[c] = acc[c];
    }
}

// ---------------- merge: float4 sum over runs, divide by per-head D ----------------
__global__ __launch_bounds__(256) void merge_kernel() {
    int n = (blockIdx.x * blockDim.x + threadIdx.x) >> 5;
    int lane = threadIdx.x & 31;
    if (n >= NN) return;

    float4 O = make_float4(0.f, 0.f, 0.f, 0.f);
    int base = n * RR;
    for (int r = 0; r < RR; r++) {
        int ridx = g_runidx[base + r];
        if (ridx < 0) continue;
        float4 v = ((const float4*)(g_Vr + (size_t)ridx * 128))[lane];
        O.x += v.x; O.y += v.y; O.z += v.z; O.w += v.w;
    }
    float d = g_D[(size_t)n * 4 + (lane >> 3)];
    float inv = (d > 0.f) ? 1.f / d : 0.f;
    ((float4*)(g_aggr + (size_t)n * 128))[lane] =
        make_float4(O.x * inv, O.y * inv, O.z * inv, O.w * inv);
}

// ---------------- host ----------------
extern "C" void kernel_launch(void* const* d_in, const int* in_sizes, int n_in,
                              void* d_out, int out_size) {
    const float* emb   = (const float*)d_in[0];
    const float* W_kqv = (const float*)d_in[1];
    const float* b_kqv = (const float*)d_in[2];
    const float* Wk    = (const float*)d_in[3];
    const float* Wv    = (const float*)d_in[4];
    const float* p_rel = (const float*)d_in[5];
    const float* W_out = (const float*)d_in[6];
    const float* b_out = (const float*)d_in[7];
    const float* skip  = (const float*)d_in[8];
    const int*   x     = (const int*)d_in[9];
    const int*   ei    = (const int*)d_in[10];
    const int*   et    = (const int*)d_in[11];
    float* out = (float*)d_out;

    const int SMEM_QT = (4096 + 64 * 129) * 4;           // 49408
    static bool attr_set = false;
    if (!attr_set) {
        cudaFuncSetAttribute(kqv_wmma_kernel, cudaFuncAttributeMaxDynamicSharedMemorySize, SMEM_WMMA);
        cudaFuncSetAttribute(out_wmma_kernel, cudaFuncAttributeMaxDynamicSharedMemorySize, SMEM_WMMA);
        cudaFuncSetAttribute(qt_kernel, cudaFuncAttributeMaxDynamicSharedMemorySize, SMEM_QT);
        cudaFuncSetAttribute(vt_kernel, cudaFuncAttributeMaxDynamicSharedMemorySize, SMEM_QT);
        attr_set = true;
    }

    const int nblocks_nh  = (NN * HID + 255) / 256;
    const int nblocks_tc  = (NN + 127) / 128;            // 782
    const int nblocks_qt  = (NN + 63) / 64;              // 1563
    const int nblocks_e   = (EE + 255) / 256;
    const int nblocks_kb  = (KB + 255) / 256;
    const int nblocks_kb1 = (KB + 1 + 255) / 256;
    const int nblocks_w   = (NN * 32 + 255) / 256;       // warp per node

    gather_kernel<<<nblocks_nh, 256>>>(emb, x);

    // sort edges by (dst, rel) into CSR + compact run lists
    zero_deg_kernel<<<nblocks_kb, 256>>>();
    hist_kernel<<<nblocks_e, 256>>>(ei, et);
    scan1_kernel<<<NB2, 1024>>>();
    scan2_kernel<<<1, 1024>>>();
    scan3_kernel<<<nblocks_kb1, 256>>>();
    scatter_kernel<<<nblocks_e, 256>>>(ei, et);
    build_lists_kernel<<<nblocks_kb, 256>>>();

    dim3 tg(nblocks_qt, RR);
    for (int l = 0; l < LL; l++) {
        const float* Wkqv_l = W_kqv + (size_t)l * HID * 3 * HID;
        const float* bkqv_l = b_kqv + (size_t)l * 3 * HID;
        const float* Wk_l   = Wk + (size_t)l * RR * HH * DD * DD;
        const float* Wv_l   = Wv + (size_t)l * RR * HH * DD * DD;
        const float* pr_l   = p_rel + (size_t)l * RR * HH;
        const float* Wout_l = W_out + (size_t)l * HID * HID;
        const float* bout_l = b_out + (size_t)l * HID;

        kqv_wmma_kernel<<<nblocks_tc, 256, SMEM_WMMA>>>(Wkqv_l, bkqv_l);
        qt_kernel<<<tg, 256, SMEM_QT>>>(Wk_l, pr_l);
        attn_kernel<<<nblocks_w, 256>>>();
        vt_kernel<<<tg, 256, SMEM_QT>>>(Wv_l);
        merge_kernel<<<nblocks_w, 256>>>();
        out_wmma_kernel<<<nblocks_tc, 256, SMEM_WMMA>>>(Wout_l, bout_l, skip, l,
                                                        (l == LL - 1) ? out : nullptr);
    }
}